// round 4
// baseline (speedup 1.0000x reference)
#include <cuda_runtime.h>
#include <cstdint>

__device__ double g_partials[4096];
__device__ unsigned int g_done_count = 0;

__global__ void __launch_bounds__(256)
center_loss_fused(const float* __restrict__ x,
                  const float* __restrict__ centers,
                  const int* __restrict__ labels_raw,
                  float* __restrict__ out,
                  int B, int D, int C) {
    const int lane = threadIdx.x & 31;
    const int warp_in_blk = threadIdx.x >> 5;
    const int warps_per_blk = blockDim.x >> 5;
    const int gwarp = blockIdx.x * warps_per_blk + warp_in_blk;
    const int nwarps = gridDim.x * warps_per_blk;
    const int n4 = D >> 2;

    // ---- labels dtype detection: int64 iff all odd int32 words are 0 ----
    __shared__ int s_is64;
    if (threadIdx.x < 32) {
        int nsample = B < 32 ? B : 32;
        int v = (lane < nsample) ? labels_raw[2 * lane + 1] : 0;
        unsigned any = __ballot_sync(0xFFFFFFFFu, v != 0);
        if (lane == 0) s_is64 = (any == 0);
    }
    __syncthreads();
    const int is64 = s_is64;

    double local = 0.0;

    if (n4 == 128) {
        // D=512 fast path, 2 rows per warp iteration, software-pipelined:
        // labels + all x loads issued first (front-batched LDG), x-norms
        // computed during the label->center dependency round-trip, then all
        // center loads batched.
        for (int row = gwarp * 2; row < B; row += nwarps * 2) {
            const int r0 = row;
            const int r1 = (row + 1 < B) ? row + 1 : row;   // degenerate dup guard

            // phase 0: issue label loads + all x loads
            long long l0 = is64 ? ((const long long*)labels_raw)[r0]
                                : (long long)labels_raw[r0];
            long long l1 = is64 ? ((const long long*)labels_raw)[r1]
                                : (long long)labels_raw[r1];

            const float4* __restrict__ xr0 =
                reinterpret_cast<const float4*>(x + (size_t)r0 * D);
            const float4* __restrict__ xr1 =
                reinterpret_cast<const float4*>(x + (size_t)r1 * D);

            float4 a0[4], a1[4];
            #pragma unroll
            for (int k = 0; k < 4; k++) a0[k] = xr0[lane + k * 32];
            #pragma unroll
            for (int k = 0; k < 4; k++) a1[k] = xr1[lane + k * 32];

            // phase 1: x-norms (overlaps label round-trip)
            float xsq0 = 0.f, xsq1 = 0.f;
            #pragma unroll
            for (int k = 0; k < 4; k++) {
                xsq0 = fmaf(a0[k].x, a0[k].x, fmaf(a0[k].y, a0[k].y,
                        fmaf(a0[k].z, a0[k].z, fmaf(a0[k].w, a0[k].w, xsq0))));
                xsq1 = fmaf(a1[k].x, a1[k].x, fmaf(a1[k].y, a1[k].y,
                        fmaf(a1[k].z, a1[k].z, fmaf(a1[k].w, a1[k].w, xsq1))));
            }

            // phase 2: issue ALL center loads back-to-back (MLP=8)
            if (l0 < 0) l0 = 0; if (l0 >= C) l0 = C - 1;
            if (l1 < 0) l1 = 0; if (l1 >= C) l1 = C - 1;
            const float4* __restrict__ cr0 =
                reinterpret_cast<const float4*>(centers + (size_t)l0 * D);
            const float4* __restrict__ cr1 =
                reinterpret_cast<const float4*>(centers + (size_t)l1 * D);

            float4 b0[4], b1[4];
            #pragma unroll
            for (int k = 0; k < 4; k++) b0[k] = cr0[lane + k * 32];
            #pragma unroll
            for (int k = 0; k < 4; k++) b1[k] = cr1[lane + k * 32];

            // phase 3: dots + center norms
            float dot0 = 0.f, dot1 = 0.f, csq0 = 0.f, csq1 = 0.f;
            #pragma unroll
            for (int k = 0; k < 4; k++) {
                dot0 = fmaf(a0[k].x, b0[k].x, fmaf(a0[k].y, b0[k].y,
                        fmaf(a0[k].z, b0[k].z, fmaf(a0[k].w, b0[k].w, dot0))));
                csq0 = fmaf(b0[k].x, b0[k].x, fmaf(b0[k].y, b0[k].y,
                        fmaf(b0[k].z, b0[k].z, fmaf(b0[k].w, b0[k].w, csq0))));
                dot1 = fmaf(a1[k].x, b1[k].x, fmaf(a1[k].y, b1[k].y,
                        fmaf(a1[k].z, b1[k].z, fmaf(a1[k].w, b1[k].w, dot1))));
                csq1 = fmaf(b1[k].x, b1[k].x, fmaf(b1[k].y, b1[k].y,
                        fmaf(b1[k].z, b1[k].z, fmaf(b1[k].w, b1[k].w, csq1))));
            }

            // warp reduce all 6 partials (packed in pairs to halve shuffles)
            #pragma unroll
            for (int o = 16; o > 0; o >>= 1) {
                dot0 += __shfl_down_sync(0xFFFFFFFFu, dot0, o);
                xsq0 += __shfl_down_sync(0xFFFFFFFFu, xsq0, o);
                csq0 += __shfl_down_sync(0xFFFFFFFFu, csq0, o);
                dot1 += __shfl_down_sync(0xFFFFFFFFu, dot1, o);
                xsq1 += __shfl_down_sync(0xFFFFFFFFu, xsq1, o);
                csq1 += __shfl_down_sync(0xFFFFFFFFu, csq1, o);
            }
            if (lane == 0) {
                float v0 = 0.5f * (xsq0 + csq0) + 0.3f * dot0;
                v0 = fminf(fmaxf(v0, 1e-12f), 1e12f);
                local += (double)v0;
                if (r1 != r0) {
                    float v1 = 0.5f * (xsq1 + csq1) + 0.3f * dot1;
                    v1 = fminf(fmaxf(v1, 1e-12f), 1e12f);
                    local += (double)v1;
                }
            }
        }
    } else {
        // generic fallback
        for (int row = gwarp; row < B; row += nwarps) {
            long long li = is64 ? ((const long long*)labels_raw)[row]
                                : (long long)labels_raw[row];
            if (li < 0) li = 0;
            if (li >= C) li = C - 1;
            const float4* xr = reinterpret_cast<const float4*>(x + (size_t)row * D);
            const float4* cr = reinterpret_cast<const float4*>(centers + (size_t)li * D);
            float dot = 0.f, xsq = 0.f, csq = 0.f;
            for (int i = lane; i < n4; i += 32) {
                float4 a = xr[i];
                float4 b = cr[i];
                dot = fmaf(a.x, b.x, fmaf(a.y, b.y, fmaf(a.z, b.z, fmaf(a.w, b.w, dot))));
                xsq = fmaf(a.x, a.x, fmaf(a.y, a.y, fmaf(a.z, a.z, fmaf(a.w, a.w, xsq))));
                csq = fmaf(b.x, b.x, fmaf(b.y, b.y, fmaf(b.z, b.z, fmaf(b.w, b.w, csq))));
            }
            #pragma unroll
            for (int o = 16; o > 0; o >>= 1) {
                dot += __shfl_down_sync(0xFFFFFFFFu, dot, o);
                xsq += __shfl_down_sync(0xFFFFFFFFu, xsq, o);
                csq += __shfl_down_sync(0xFFFFFFFFu, csq, o);
            }
            if (lane == 0) {
                float v = 0.5f * (xsq + csq) + 0.3f * dot;
                v = fminf(fmaxf(v, 1e-12f), 1e12f);
                local += (double)v;
            }
        }
    }

    // ---- block partial (double, deterministic) ----
    __shared__ double sdata[32];
    if (lane == 0) sdata[warp_in_blk] = local;
    __syncthreads();
    if (threadIdx.x == 0) {
        double s = 0.0;
        for (int i = 0; i < warps_per_blk; i++) s += sdata[i];
        g_partials[blockIdx.x] = s;
    }

    // ---- last-block-done final reduction ----
    __shared__ bool s_last;
    __threadfence();
    if (threadIdx.x == 0) {
        unsigned int prev = atomicAdd(&g_done_count, 1u);
        s_last = (prev == gridDim.x - 1);
    }
    __syncthreads();
    if (s_last) {
        __shared__ double fin[256];
        double s = 0.0;
        for (int i = threadIdx.x; i < gridDim.x; i += blockDim.x)
            s += g_partials[i];
        fin[threadIdx.x] = s;
        __syncthreads();
        for (int o = blockDim.x >> 1; o > 0; o >>= 1) {
            if (threadIdx.x < (unsigned)o) fin[threadIdx.x] += fin[threadIdx.x + o];
            __syncthreads();
        }
        if (threadIdx.x == 0) {
            double masked_zeros = ((double)B * (double)C - (double)B) * 1e-12;
            out[0] = (float)((fin[0] + masked_zeros) / (double)B);
            g_done_count = 0;  // reset for next graph replay
        }
    }
}

extern "C" void kernel_launch(void* const* d_in, const int* in_sizes, int n_in,
                              void* d_out, int out_size) {
    const float* x = (const float*)d_in[0];
    const float* centers = (const float*)d_in[1];
    const int* labels = (const int*)d_in[2];
    float* out = (float*)d_out;

    const int B = in_sizes[2];
    const int D = in_sizes[0] / B;
    const int C = in_sizes[1] / D;

    const int threads = 256;   // 8 warps/block
    const int warps_per_blk = threads / 32;
    const int rows_per_warp = (D == 512) ? 2 : 1;
    int warps_needed = (B + rows_per_warp - 1) / rows_per_warp;
    int blocks = (warps_needed + warps_per_blk - 1) / warps_per_blk;
    if (blocks > 4096) blocks = 4096;
    if (blocks < 1) blocks = 1;

    center_loss_fused<<<blocks, threads>>>(x, centers, labels, out, B, D, C);
}